// round 6
// baseline (speedup 1.0000x reference)
#include <cuda_runtime.h>
#include <cuda_bf16.h>

#define NN 100000   // nodes
#define NE 800000   // edges
#define NG 256      // graphs
#define C  96       // channels (in/hid)
#define OC 16       // out channels
#define NBLK 98     // ceil(NN/1024) for scan

// ---------------- static device scratch ----------------
__device__ __align__(16) float g_dinv[NN];
__device__ __align__(16) float g_h  [NN * C];   // GEMM output of current layer
__device__ __align__(16) float g_act[NN * C];   // aggregated/activated -> next layer in
__device__ __align__(16) float g_agg[NN * C];   // layer-3 aggregation (pre-pool)
__device__ __align__(8)  int2  g_adj[NE];       // CSR records: {src, coef_bits}
__device__ int g_deg[NN];
__device__ int g_rowptr[NN + 1];
__device__ int g_cur[NN];
__device__ int g_bsum[NBLK + 2];
__device__ int g_gstart[NG + 1];

// ---------------- packed f32x2 helpers (Blackwell FFMA2 via PTX) ----------------
__device__ __forceinline__ void ffma2(unsigned long long& d, unsigned long long a,
                                      unsigned long long b) {
    asm("fma.rn.f32x2 %0, %1, %2, %0;" : "+l"(d) : "l"(a), "l"(b));
}
__device__ __forceinline__ unsigned long long bcast2(float x) {
    unsigned long long r;
    asm("mov.b64 %0, {%1, %1};" : "=l"(r) : "r"(__float_as_uint(x)));
    return r;
}

// ---------------- prelude: zero degrees + graph segment starts ----------------
__global__ void k_prelude(const int* __restrict__ batch) {
    int i = blockIdx.x * blockDim.x + threadIdx.x;
    if (i >= NN) return;
    g_deg[i] = 0;
    int b = batch[i];
    int bp = (i == 0) ? -1 : batch[i - 1];
    for (int g = bp + 1; g <= b; g++) g_gstart[g] = i;
    if (i == NN - 1)
        for (int g = b + 1; g <= NG; g++) g_gstart[g] = NN;
}

// ---------------- degree histogram ----------------
__global__ void k_hist(const int* __restrict__ ei) {
    int e = blockIdx.x * blockDim.x + threadIdx.x;
    if (e < NE) atomicAdd(&g_deg[ei[NE + e]], 1);   // in-degree at dst
}

// ---------------- scan phase 1 (+ fused dinv) ----------------
__global__ __launch_bounds__(1024) void k_scan1() {
    __shared__ int s[1024];
    int tid = threadIdx.x;
    int i = blockIdx.x * 1024 + tid;
    int v = (i < NN) ? g_deg[i] : 0;
    if (i < NN) g_dinv[i] = rsqrtf((float)v + 1.0f);   // +1 self-loop
    s[tid] = v;
    __syncthreads();
#pragma unroll
    for (int off = 1; off < 1024; off <<= 1) {
        int t = (tid >= off) ? s[tid - off] : 0;
        __syncthreads();
        s[tid] += t;
        __syncthreads();
    }
    if (i < NN) g_rowptr[i] = s[tid] - v;     // exclusive within block
    if (tid == 1023) g_bsum[blockIdx.x] = s[1023];
}

// ---------------- scan phases 2+3 fused: per-block parallel offset ----------------
__global__ __launch_bounds__(1024) void k_scan23() {
    __shared__ int s[128];
    int tid = threadIdx.x;
    int bid = blockIdx.x;
    if (tid < 128) s[tid] = (tid < bid) ? g_bsum[tid] : 0;   // bid <= 97 < 128
    __syncthreads();
#pragma unroll
    for (int off = 64; off > 0; off >>= 1) {
        if (tid < off) s[tid] += s[tid + off];
        __syncthreads();
    }
    int boff = s[0];
    int i = bid * 1024 + tid;
    if (i < NN) {
        g_rowptr[i] += boff;
        g_cur[i] = 0;
    }
    if (bid == 0 && tid == 0) g_rowptr[NN] = NE;
}

// ---------------- CSR fill: adj[pos] = {src, dinv[src]*dinv[dst]} ----------------
__global__ void k_fill(const int* __restrict__ ei) {
    int e = blockIdx.x * blockDim.x + threadIdx.x;
    if (e >= NE) return;
    int src = ei[e];
    int dst = ei[NE + e];
    int pos = g_rowptr[dst] + atomicAdd(&g_cur[dst], 1);
    g_adj[pos] = make_int2(src, __float_as_int(g_dinv[src] * g_dinv[dst]));
}

// ---------------- GEMM: g_h = in @ W (f32x2, 2 rows x 16 cols/thread) ----------------
__device__ __forceinline__ float f4c(const float4& v, int k) {
    return k == 0 ? v.x : (k == 1 ? v.y : (k == 2 ? v.z : v.w));
}

__global__ __launch_bounds__(192) void k_gemm(const float* __restrict__ xin,
                                              const float* __restrict__ W,
                                              int use_act) {
    __shared__ __align__(16) float Ws[C * C];
    const float* in = use_act ? (const float*)g_act : xin;
    int tid = threadIdx.x;
    for (int i = tid; i < C * C / 4; i += 192)
        reinterpret_cast<float4*>(Ws)[i] = reinterpret_cast<const float4*>(W)[i];
    __syncthreads();

    int rs = tid / 6;          // 0..31  row slot
    int cg = tid - rs * 6;     // 0..5   col group (16 cols = 8 packed pairs)
    int row0 = blockIdx.x * 64 + rs * 2;

    unsigned long long acc[2][8];      // 2 rows x 8 f32x2 pairs
#pragma unroll
    for (int r = 0; r < 2; r++)
#pragma unroll
        for (int c = 0; c < 8; c++) acc[r][c] = 0ull;

#pragma unroll 2
    for (int k4 = 0; k4 < C / 4; k4++) {
        float4 xv[2];
#pragma unroll
        for (int r = 0; r < 2; r++) {
            int row = row0 + r;
            xv[r] = (row < NN)
                ? __ldg(reinterpret_cast<const float4*>(in + (size_t)row * C + k4 * 4))
                : make_float4(0.f, 0.f, 0.f, 0.f);
        }
#pragma unroll
        for (int kk = 0; kk < 4; kk++) {
            const ulonglong2* wrow =
                reinterpret_cast<const ulonglong2*>(&Ws[(k4 * 4 + kk) * C + cg * 16]);
            ulonglong2 wv[4];
#pragma unroll
            for (int c4 = 0; c4 < 4; c4++) wv[c4] = wrow[c4];
#pragma unroll
            for (int r = 0; r < 2; r++) {
                unsigned long long xp = bcast2(f4c(xv[r], kk));
#pragma unroll
                for (int c4 = 0; c4 < 4; c4++) {
                    ffma2(acc[r][c4 * 2 + 0], xp, wv[c4].x);
                    ffma2(acc[r][c4 * 2 + 1], xp, wv[c4].y);
                }
            }
        }
    }

#pragma unroll
    for (int r = 0; r < 2; r++) {
        int row = row0 + r;
        if (row >= NN) continue;
        ulonglong2* hp = reinterpret_cast<ulonglong2*>(g_h + (size_t)row * C + cg * 16);
#pragma unroll
        for (int c4 = 0; c4 < 4; c4++)
            hp[c4] = make_ulonglong2(acc[r][c4 * 2 + 0], acc[r][c4 * 2 + 1]);
    }
}

// ---------------- pull aggregation (fused bias + optional relu) ----------------
__global__ void k_gather(const float* __restrict__ bias, int relu) {
    int idx = blockIdx.x * blockDim.x + threadIdx.x;   // over NN*12
    if (idx >= NN * 12) return;
    int node = idx / 12;
    int c = idx - node * 12;          // 0..11 -> float4 chunks 2c, 2c+1

    const float4* hp = reinterpret_cast<const float4*>(g_h);
    float di = g_dinv[node];
    float d2 = di * di;
    float4 s0 = hp[node * 24 + 2 * c];
    float4 s1 = hp[node * 24 + 2 * c + 1];
    float4 a0 = make_float4(s0.x * d2, s0.y * d2, s0.z * d2, s0.w * d2);
    float4 a1 = make_float4(s1.x * d2, s1.y * d2, s1.z * d2, s1.w * d2);

    int beg = g_rowptr[node];
    int end = g_rowptr[node + 1];
    for (int j = beg; j < end; j++) {
        int2 rec = __ldg(&g_adj[j]);
        float cf = __int_as_float(rec.y);
        float4 v0 = hp[rec.x * 24 + 2 * c];
        float4 v1 = hp[rec.x * 24 + 2 * c + 1];
        a0.x = fmaf(v0.x, cf, a0.x); a0.y = fmaf(v0.y, cf, a0.y);
        a0.z = fmaf(v0.z, cf, a0.z); a0.w = fmaf(v0.w, cf, a0.w);
        a1.x = fmaf(v1.x, cf, a1.x); a1.y = fmaf(v1.y, cf, a1.y);
        a1.z = fmaf(v1.z, cf, a1.z); a1.w = fmaf(v1.w, cf, a1.w);
    }

    float4 b0 = __ldg(reinterpret_cast<const float4*>(bias) + 2 * c);
    float4 b1 = __ldg(reinterpret_cast<const float4*>(bias) + 2 * c + 1);
    a0.x += b0.x; a0.y += b0.y; a0.z += b0.z; a0.w += b0.w;
    a1.x += b1.x; a1.y += b1.y; a1.z += b1.z; a1.w += b1.w;

    float4* dst = relu ? reinterpret_cast<float4*>(g_act)
                       : reinterpret_cast<float4*>(g_agg);
    if (relu) {
        a0.x = fmaxf(a0.x, 0.f); a0.y = fmaxf(a0.y, 0.f);
        a0.z = fmaxf(a0.z, 0.f); a0.w = fmaxf(a0.w, 0.f);
        a1.x = fmaxf(a1.x, 0.f); a1.y = fmaxf(a1.y, 0.f);
        a1.z = fmaxf(a1.z, 0.f); a1.w = fmaxf(a1.w, 0.f);
    }
    dst[node * 24 + 2 * c] = a0;
    dst[node * 24 + 2 * c + 1] = a1;
}

// ---------------- fused mean-pool + head GEMM (one block per graph) ----------------
__global__ __launch_bounds__(96) void k_poolhead(const float* __restrict__ Wlin,
                                                 float* __restrict__ out) {
    __shared__ float p[C];
    int g = blockIdx.x;
    int c = threadIdx.x;                 // 0..95 channel
    int beg = g_gstart[g], end = g_gstart[g + 1];
    float acc = 0.f;
    for (int n = beg; n < end; n++)
        acc += g_agg[(size_t)n * C + c];
    float cnt = (float)(end - beg);
    p[c] = acc / fmaxf(cnt, 1.0f);
    __syncthreads();
    if (c < OC) {
        float s = 0.f;
#pragma unroll
        for (int k = 0; k < C; k++)
            s = fmaf(p[k], __ldg(Wlin + k * OC + c), s);
        out[g * OC + c] = s;
    }
}

// ---------------- launch ----------------
extern "C" void kernel_launch(void* const* d_in, const int* in_sizes, int n_in,
                              void* d_out, int out_size) {
    const float* x     = (const float*)d_in[0];
    const int*   ei    = (const int*)d_in[1];     // int32 (JAX x64 disabled)
    const int*   batch = (const int*)d_in[2];     // int32
    const float* W1    = (const float*)d_in[3];
    const float* b1    = (const float*)d_in[4];
    const float* W2    = (const float*)d_in[5];
    const float* b2    = (const float*)d_in[6];
    const float* W3    = (const float*)d_in[7];
    const float* b3    = (const float*)d_in[8];
    const float* Wlin  = (const float*)d_in[9];
    float* out = (float*)d_out;

    const int TB = 256;
    int gN  = (NN + TB - 1) / TB;
    int gE  = (NE + TB - 1) / TB;
    int gNC = (NN * 12 + TB - 1) / TB;
    int gGemm = (NN + 63) / 64;

    // CSR build (5 launches, int atomics only)
    k_prelude<<<gN, TB>>>(batch);        // 0
    k_hist<<<gE, TB>>>(ei);              // 1
    k_scan1<<<NBLK, 1024>>>();           // 2
    k_scan23<<<NBLK, 1024>>>();          // 3
    k_fill<<<gE, TB>>>(ei);              // 4

    // layer 1
    k_gemm<<<gGemm, 192>>>(x, W1, 0);    // 5  <- likely ncu window
    k_gather<<<gNC, TB>>>(b1, 1);        // 6
    // layer 2
    k_gemm<<<gGemm, 192>>>(nullptr, W2, 1);
    k_gather<<<gNC, TB>>>(b2, 1);
    // layer 3
    k_gemm<<<gGemm, 192>>>(nullptr, W3, 1);
    k_gather<<<gNC, TB>>>(b3, 0);

    // pooled mean + head
    k_poolhead<<<NG, 96>>>(Wlin, out);
}

// round 7
// speedup vs baseline: 1.3723x; 1.3723x over previous
#include <cuda_runtime.h>
#include <cuda_bf16.h>

#define NN 100000   // nodes
#define NE 800000   // edges
#define NG 256      // graphs
#define C  96       // channels (in/hid)
#define OC 16       // out channels
#define NBLK 98     // ceil(NN/1024) for scan

// ---------------- static device scratch ----------------
__device__ __align__(16) float g_dinv[NN];
__device__ __align__(16) float g_h  [NN * C];   // GEMM output of current layer
__device__ __align__(16) float g_act[NN * C];   // aggregated/activated -> next layer in
__device__ __align__(16) float g_agg[NN * C];   // layer-3 aggregation (pre-pool)
__device__ __align__(8)  int2  g_adj[NE];       // CSR records: {src, coef_bits}
__device__ int g_deg[NN];
__device__ int g_rowptr[NN + 1];
__device__ int g_cur[NN];
__device__ int g_bsum[NBLK + 2];
__device__ int g_gstart[NG + 1];

// ---------------- packed f32x2 helpers (Blackwell FFMA2 via PTX) ----------------
__device__ __forceinline__ void ffma2(unsigned long long& d, unsigned long long a,
                                      unsigned long long b) {
    asm("fma.rn.f32x2 %0, %1, %2, %0;" : "+l"(d) : "l"(a), "l"(b));
}
__device__ __forceinline__ unsigned long long bcast2(float x) {
    unsigned long long r;
    asm("mov.b64 %0, {%1, %1};" : "=l"(r) : "r"(__float_as_uint(x)));
    return r;
}

// ---------------- prelude: zero degrees + graph segment starts ----------------
__global__ void k_prelude(const int* __restrict__ batch) {
    int i = blockIdx.x * blockDim.x + threadIdx.x;
    if (i >= NN) return;
    g_deg[i] = 0;
    int b = batch[i];
    int bp = (i == 0) ? -1 : batch[i - 1];
    for (int g = bp + 1; g <= b; g++) g_gstart[g] = i;
    if (i == NN - 1)
        for (int g = b + 1; g <= NG; g++) g_gstart[g] = NN;
}

// ---------------- degree histogram ----------------
__global__ void k_hist(const int* __restrict__ ei) {
    int e = blockIdx.x * blockDim.x + threadIdx.x;
    if (e < NE) atomicAdd(&g_deg[ei[NE + e]], 1);   // in-degree at dst
}

// ---------------- scan phase 1 (+ fused dinv) ----------------
__global__ __launch_bounds__(1024) void k_scan1() {
    __shared__ int s[1024];
    int tid = threadIdx.x;
    int i = blockIdx.x * 1024 + tid;
    int v = (i < NN) ? g_deg[i] : 0;
    if (i < NN) g_dinv[i] = rsqrtf((float)v + 1.0f);   // +1 self-loop
    s[tid] = v;
    __syncthreads();
#pragma unroll
    for (int off = 1; off < 1024; off <<= 1) {
        int t = (tid >= off) ? s[tid - off] : 0;
        __syncthreads();
        s[tid] += t;
        __syncthreads();
    }
    if (i < NN) g_rowptr[i] = s[tid] - v;     // exclusive within block
    if (tid == 1023) g_bsum[blockIdx.x] = s[1023];
}

// ---------------- scan phases 2+3 fused: per-block parallel offset ----------------
__global__ __launch_bounds__(1024) void k_scan23() {
    __shared__ int s[128];
    int tid = threadIdx.x;
    int bid = blockIdx.x;
    if (tid < 128) s[tid] = (tid < bid) ? g_bsum[tid] : 0;   // bid <= 97 < 128
    __syncthreads();
#pragma unroll
    for (int off = 64; off > 0; off >>= 1) {
        if (tid < off) s[tid] += s[tid + off];
        __syncthreads();
    }
    int boff = s[0];
    int i = bid * 1024 + tid;
    if (i < NN) {
        g_rowptr[i] += boff;
        g_cur[i] = 0;
    }
    if (bid == 0 && tid == 0) g_rowptr[NN] = NE;
}

// ---------------- CSR fill: adj[pos] = {src, dinv[src]*dinv[dst]} ----------------
__global__ void k_fill(const int* __restrict__ ei) {
    int e = blockIdx.x * blockDim.x + threadIdx.x;
    if (e >= NE) return;
    int src = ei[e];
    int dst = ei[NE + e];
    int pos = g_rowptr[dst] + atomicAdd(&g_cur[dst], 1);
    g_adj[pos] = make_int2(src, __float_as_int(g_dinv[src] * g_dinv[dst]));
}

// ---------------- GEMM: g_h = in @ W (f32x2, 4 rows x 16 cols/thread) ----------------
__device__ __forceinline__ float f4c(const float4& v, int k) {
    return k == 0 ? v.x : (k == 1 ? v.y : (k == 2 ? v.z : v.w));
}

__global__ __launch_bounds__(192) void k_gemm(const float* __restrict__ xin,
                                              const float* __restrict__ W,
                                              int use_act) {
    __shared__ __align__(16) float Ws[C * C];
    const float* in = use_act ? (const float*)g_act : xin;
    int tid = threadIdx.x;
    for (int i = tid; i < C * C / 4; i += 192)
        reinterpret_cast<float4*>(Ws)[i] = reinterpret_cast<const float4*>(W)[i];
    __syncthreads();

    int rs = tid / 6;          // 0..31  row slot
    int cg = tid - rs * 6;     // 0..5   col group (16 cols = 8 packed pairs)
    int row0 = blockIdx.x * 128 + rs * 4;

    unsigned long long acc[4][8];      // 4 rows x 8 f32x2 pairs (16 cols)
#pragma unroll
    for (int r = 0; r < 4; r++)
#pragma unroll
        for (int c = 0; c < 8; c++) acc[r][c] = 0ull;

#pragma unroll 2
    for (int k4 = 0; k4 < C / 4; k4++) {
        float4 xv[4];
#pragma unroll
        for (int r = 0; r < 4; r++) {
            int row = row0 + r;
            xv[r] = (row < NN)
                ? __ldg(reinterpret_cast<const float4*>(in + (size_t)row * C + k4 * 4))
                : make_float4(0.f, 0.f, 0.f, 0.f);
        }
#pragma unroll
        for (int kk = 0; kk < 4; kk++) {
            const ulonglong2* wrow =
                reinterpret_cast<const ulonglong2*>(&Ws[(k4 * 4 + kk) * C + cg * 16]);
            ulonglong2 wv[4];
#pragma unroll
            for (int c4 = 0; c4 < 4; c4++) wv[c4] = wrow[c4];
#pragma unroll
            for (int r = 0; r < 4; r++) {
                unsigned long long xp = bcast2(f4c(xv[r], kk));
#pragma unroll
                for (int c4 = 0; c4 < 4; c4++) {
                    ffma2(acc[r][c4 * 2 + 0], xp, wv[c4].x);
                    ffma2(acc[r][c4 * 2 + 1], xp, wv[c4].y);
                }
            }
        }
    }

#pragma unroll
    for (int r = 0; r < 4; r++) {
        int row = row0 + r;
        if (row >= NN) continue;
        ulonglong2* hp = reinterpret_cast<ulonglong2*>(g_h + (size_t)row * C + cg * 16);
#pragma unroll
        for (int c4 = 0; c4 < 4; c4++)
            hp[c4] = make_ulonglong2(acc[r][c4 * 2 + 0], acc[r][c4 * 2 + 1]);
    }
}

// ---------------- pull aggregation (fused bias + optional relu) ----------------
__global__ void k_gather(const float* __restrict__ bias, int relu) {
    int idx = blockIdx.x * blockDim.x + threadIdx.x;   // over NN*12
    if (idx >= NN * 12) return;
    int node = idx / 12;
    int c = idx - node * 12;          // 0..11 -> float4 chunks 2c, 2c+1

    const float4* hp = reinterpret_cast<const float4*>(g_h);
    float di = g_dinv[node];
    float d2 = di * di;
    float4 s0 = hp[node * 24 + 2 * c];
    float4 s1 = hp[node * 24 + 2 * c + 1];
    float4 a0 = make_float4(s0.x * d2, s0.y * d2, s0.z * d2, s0.w * d2);
    float4 a1 = make_float4(s1.x * d2, s1.y * d2, s1.z * d2, s1.w * d2);

    int beg = g_rowptr[node];
    int end = g_rowptr[node + 1];
    for (int j = beg; j < end; j++) {
        int2 rec = __ldg(&g_adj[j]);
        float cf = __int_as_float(rec.y);
        float4 v0 = hp[rec.x * 24 + 2 * c];
        float4 v1 = hp[rec.x * 24 + 2 * c + 1];
        a0.x = fmaf(v0.x, cf, a0.x); a0.y = fmaf(v0.y, cf, a0.y);
        a0.z = fmaf(v0.z, cf, a0.z); a0.w = fmaf(v0.w, cf, a0.w);
        a1.x = fmaf(v1.x, cf, a1.x); a1.y = fmaf(v1.y, cf, a1.y);
        a1.z = fmaf(v1.z, cf, a1.z); a1.w = fmaf(v1.w, cf, a1.w);
    }

    float4 b0 = __ldg(reinterpret_cast<const float4*>(bias) + 2 * c);
    float4 b1 = __ldg(reinterpret_cast<const float4*>(bias) + 2 * c + 1);
    a0.x += b0.x; a0.y += b0.y; a0.z += b0.z; a0.w += b0.w;
    a1.x += b1.x; a1.y += b1.y; a1.z += b1.z; a1.w += b1.w;

    float4* dst = relu ? reinterpret_cast<float4*>(g_act)
                       : reinterpret_cast<float4*>(g_agg);
    if (relu) {
        a0.x = fmaxf(a0.x, 0.f); a0.y = fmaxf(a0.y, 0.f);
        a0.z = fmaxf(a0.z, 0.f); a0.w = fmaxf(a0.w, 0.f);
        a1.x = fmaxf(a1.x, 0.f); a1.y = fmaxf(a1.y, 0.f);
        a1.z = fmaxf(a1.z, 0.f); a1.w = fmaxf(a1.w, 0.f);
    }
    dst[node * 24 + 2 * c] = a0;
    dst[node * 24 + 2 * c + 1] = a1;
}

// ---------------- fused mean-pool + head GEMM (one block per graph) ----------------
__global__ __launch_bounds__(96) void k_poolhead(const float* __restrict__ Wlin,
                                                 float* __restrict__ out) {
    __shared__ float p[C];
    int g = blockIdx.x;
    int c = threadIdx.x;                 // 0..95 channel
    int beg = g_gstart[g], end = g_gstart[g + 1];
    float acc = 0.f;
    for (int n = beg; n < end; n++)
        acc += g_agg[(size_t)n * C + c];
    float cnt = (float)(end - beg);
    p[c] = acc / fmaxf(cnt, 1.0f);
    __syncthreads();
    if (c < OC) {
        float s = 0.f;
#pragma unroll
        for (int k = 0; k < C; k++)
            s = fmaf(p[k], __ldg(Wlin + k * OC + c), s);
        out[g * OC + c] = s;
    }
}

// ---------------- launch ----------------
extern "C" void kernel_launch(void* const* d_in, const int* in_sizes, int n_in,
                              void* d_out, int out_size) {
    const float* x     = (const float*)d_in[0];
    const int*   ei    = (const int*)d_in[1];     // int32 (JAX x64 disabled)
    const int*   batch = (const int*)d_in[2];     // int32
    const float* W1    = (const float*)d_in[3];
    const float* b1    = (const float*)d_in[4];
    const float* W2    = (const float*)d_in[5];
    const float* b2    = (const float*)d_in[6];
    const float* W3    = (const float*)d_in[7];
    const float* b3    = (const float*)d_in[8];
    const float* Wlin  = (const float*)d_in[9];
    float* out = (float*)d_out;

    const int TB = 256;
    int gN  = (NN + TB - 1) / TB;
    int gE  = (NE + TB - 1) / TB;
    int gNC = (NN * 12 + TB - 1) / TB;
    int gGemm = (NN + 127) / 128;

    // CSR build interleaved with layer-1 GEMM (gemm1 independent of CSR;
    // placed at launch index 3 so the ncu window profiles it)
    k_prelude<<<gN, TB>>>(batch);           // 0
    k_hist<<<gE, TB>>>(ei);                 // 1
    k_scan1<<<NBLK, 1024>>>();              // 2
    k_gemm<<<gGemm, 192>>>(x, W1, 0);       // 3  <- ncu window
    k_scan23<<<NBLK, 1024>>>();             // 4
    k_fill<<<gE, TB>>>(ei);                 // 5

    // layer 1 aggregation
    k_gather<<<gNC, TB>>>(b1, 1);           // 6
    // layer 2
    k_gemm<<<gGemm, 192>>>(nullptr, W2, 1);
    k_gather<<<gNC, TB>>>(b2, 1);
    // layer 3
    k_gemm<<<gGemm, 192>>>(nullptr, W3, 1);
    k_gather<<<gNC, TB>>>(b3, 0);

    // pooled mean + head
    k_poolhead<<<NG, 96>>>(Wlin, out);
}

// round 8
// speedup vs baseline: 1.9817x; 1.4441x over previous
#include <cuda_runtime.h>
#include <cuda_bf16.h>

#define NN 100000   // nodes
#define NE 800000   // edges
#define NG 256      // graphs
#define C  96       // channels (in/hid)
#define OC 16       // out channels
#define NBLK 98     // ceil(NN/1024) for scan

// ---------------- static device scratch ----------------
__device__ __align__(16) float g_dinv[NN];
__device__ __align__(16) float g_h  [NN * C];   // GEMM output of current layer
__device__ __align__(16) float g_act[NN * C];   // aggregated/activated -> next layer in
__device__ __align__(16) float g_agg[NN * C];   // layer-3 aggregation (pre-pool)
__device__ __align__(8)  int2  g_adj[NE];       // CSR records: {src, coef_bits}
__device__ int g_deg[NN];
__device__ int g_rowptr[NN + 1];
__device__ int g_cur[NN];
__device__ int g_bsum[NBLK + 2];
__device__ int g_gstart[NG + 1];

// ---------------- packed f32x2 helpers (Blackwell FFMA2 via PTX) ----------------
__device__ __forceinline__ void ffma2(unsigned long long& d, unsigned long long a,
                                      unsigned long long b) {
    asm("fma.rn.f32x2 %0, %1, %2, %0;" : "+l"(d) : "l"(a), "l"(b));
}
__device__ __forceinline__ unsigned long long bcast2(float x) {
    unsigned long long r;
    asm("mov.b64 %0, {%1, %1};" : "=l"(r) : "r"(__float_as_uint(x)));
    return r;
}

// ---------------- prelude: zero degrees + graph segment starts ----------------
__global__ void k_prelude(const int* __restrict__ batch) {
    int i = blockIdx.x * blockDim.x + threadIdx.x;
    if (i >= NN) return;
    g_deg[i] = 0;
    int b = batch[i];
    int bp = (i == 0) ? -1 : batch[i - 1];
    for (int g = bp + 1; g <= b; g++) g_gstart[g] = i;
    if (i == NN - 1)
        for (int g = b + 1; g <= NG; g++) g_gstart[g] = NN;
}

// ---------------- degree histogram ----------------
__global__ void k_hist(const int* __restrict__ ei) {
    int e = blockIdx.x * blockDim.x + threadIdx.x;
    if (e < NE) atomicAdd(&g_deg[ei[NE + e]], 1);   // in-degree at dst
}

// ---------------- scan phase 1 (+ fused dinv) ----------------
__global__ __launch_bounds__(1024) void k_scan1() {
    __shared__ int s[1024];
    int tid = threadIdx.x;
    int i = blockIdx.x * 1024 + tid;
    int v = (i < NN) ? g_deg[i] : 0;
    if (i < NN) g_dinv[i] = rsqrtf((float)v + 1.0f);   // +1 self-loop
    s[tid] = v;
    __syncthreads();
#pragma unroll
    for (int off = 1; off < 1024; off <<= 1) {
        int t = (tid >= off) ? s[tid - off] : 0;
        __syncthreads();
        s[tid] += t;
        __syncthreads();
    }
    if (i < NN) g_rowptr[i] = s[tid] - v;     // exclusive within block
    if (tid == 1023) g_bsum[blockIdx.x] = s[1023];
}

// ---------------- scan phases 2+3 fused: per-block parallel offset ----------------
__global__ __launch_bounds__(1024) void k_scan23() {
    __shared__ int s[128];
    int tid = threadIdx.x;
    int bid = blockIdx.x;
    if (tid < 128) s[tid] = (tid < bid) ? g_bsum[tid] : 0;   // bid <= 97 < 128
    __syncthreads();
#pragma unroll
    for (int off = 64; off > 0; off >>= 1) {
        if (tid < off) s[tid] += s[tid + off];
        __syncthreads();
    }
    int boff = s[0];
    int i = bid * 1024 + tid;
    if (i < NN) {
        g_rowptr[i] += boff;
        g_cur[i] = 0;
    }
    if (bid == 0 && tid == 0) g_rowptr[NN] = NE;
}

// ---------------- CSR fill: adj[pos] = {src, dinv[src]*dinv[dst]} ----------------
__global__ void k_fill(const int* __restrict__ ei) {
    int e = blockIdx.x * blockDim.x + threadIdx.x;
    if (e >= NE) return;
    int src = ei[e];
    int dst = ei[NE + e];
    int pos = g_rowptr[dst] + atomicAdd(&g_cur[dst], 1);
    g_adj[pos] = make_int2(src, __float_as_int(g_dinv[src] * g_dinv[dst]));
}

// ---------------- GEMM: g_h = in @ W (f32x2, 8 rows x 8 cols/thread) ----------------
// block = 96 threads = 8 row-slabs x 12 col-groups; block covers 64 rows.
// LDS per thread per k-step = 32 B for 32 FMAs (0.5 B/FMA, half of prior tile).
__device__ __forceinline__ float f4c(const float4& v, int k) {
    return k == 0 ? v.x : (k == 1 ? v.y : (k == 2 ? v.z : v.w));
}

__global__ __launch_bounds__(96) void k_gemm(const float* __restrict__ xin,
                                             const float* __restrict__ W,
                                             int use_act) {
    __shared__ __align__(16) float Ws[C * C];
    const float* in = use_act ? (const float*)g_act : xin;
    int tid = threadIdx.x;
    for (int i = tid; i < C * C / 4; i += 96)
        reinterpret_cast<float4*>(Ws)[i] = reinterpret_cast<const float4*>(W)[i];
    __syncthreads();

    int rs = tid / 12;         // 0..7   row slab (8 rows)
    int cgi = tid - rs * 12;   // 0..11  col group (8 cols = 4 packed pairs)
    int row0 = blockIdx.x * 64 + rs * 8;

    unsigned long long acc[8][4];      // 8 rows x 4 f32x2 pairs (8 cols)
#pragma unroll
    for (int r = 0; r < 8; r++)
#pragma unroll
        for (int c = 0; c < 4; c++) acc[r][c] = 0ull;

    for (int k4 = 0; k4 < C / 4; k4++) {
        float4 xv[8];
#pragma unroll
        for (int r = 0; r < 8; r++) {
            int row = row0 + r;
            xv[r] = (row < NN)
                ? __ldg(reinterpret_cast<const float4*>(in + (size_t)row * C + k4 * 4))
                : make_float4(0.f, 0.f, 0.f, 0.f);
        }
#pragma unroll
        for (int kk = 0; kk < 4; kk++) {
            const unsigned long long* wr = reinterpret_cast<const unsigned long long*>(
                &Ws[(k4 * 4 + kk) * C + cgi * 8]);
            unsigned long long w0 = wr[0], w1 = wr[1], w2 = wr[2], w3 = wr[3];
#pragma unroll
            for (int r = 0; r < 8; r++) {
                unsigned long long xp = bcast2(f4c(xv[r], kk));
                ffma2(acc[r][0], xp, w0);
                ffma2(acc[r][1], xp, w1);
                ffma2(acc[r][2], xp, w2);
                ffma2(acc[r][3], xp, w3);
            }
        }
    }

#pragma unroll
    for (int r = 0; r < 8; r++) {
        int row = row0 + r;
        if (row >= NN) continue;
        ulonglong2* hp = reinterpret_cast<ulonglong2*>(g_h + (size_t)row * C + cgi * 8);
        hp[0] = make_ulonglong2(acc[r][0], acc[r][1]);
        hp[1] = make_ulonglong2(acc[r][2], acc[r][3]);
    }
}

// ---------------- pull aggregation (fused bias + optional relu) ----------------
__global__ void k_gather(const float* __restrict__ bias, int relu) {
    int idx = blockIdx.x * blockDim.x + threadIdx.x;   // over NN*12
    if (idx >= NN * 12) return;
    int node = idx / 12;
    int c = idx - node * 12;          // 0..11 -> float4 chunks 2c, 2c+1

    const float4* hp = reinterpret_cast<const float4*>(g_h);
    float di = g_dinv[node];
    float d2 = di * di;
    float4 s0 = hp[node * 24 + 2 * c];
    float4 s1 = hp[node * 24 + 2 * c + 1];
    float4 a0 = make_float4(s0.x * d2, s0.y * d2, s0.z * d2, s0.w * d2);
    float4 a1 = make_float4(s1.x * d2, s1.y * d2, s1.z * d2, s1.w * d2);

    int beg = g_rowptr[node];
    int end = g_rowptr[node + 1];
    for (int j = beg; j < end; j++) {
        int2 rec = __ldg(&g_adj[j]);
        float cf = __int_as_float(rec.y);
        float4 v0 = hp[rec.x * 24 + 2 * c];
        float4 v1 = hp[rec.x * 24 + 2 * c + 1];
        a0.x = fmaf(v0.x, cf, a0.x); a0.y = fmaf(v0.y, cf, a0.y);
        a0.z = fmaf(v0.z, cf, a0.z); a0.w = fmaf(v0.w, cf, a0.w);
        a1.x = fmaf(v1.x, cf, a1.x); a1.y = fmaf(v1.y, cf, a1.y);
        a1.z = fmaf(v1.z, cf, a1.z); a1.w = fmaf(v1.w, cf, a1.w);
    }

    float4 b0 = __ldg(reinterpret_cast<const float4*>(bias) + 2 * c);
    float4 b1 = __ldg(reinterpret_cast<const float4*>(bias) + 2 * c + 1);
    a0.x += b0.x; a0.y += b0.y; a0.z += b0.z; a0.w += b0.w;
    a1.x += b1.x; a1.y += b1.y; a1.z += b1.z; a1.w += b1.w;

    float4* dst = relu ? reinterpret_cast<float4*>(g_act)
                       : reinterpret_cast<float4*>(g_agg);
    if (relu) {
        a0.x = fmaxf(a0.x, 0.f); a0.y = fmaxf(a0.y, 0.f);
        a0.z = fmaxf(a0.z, 0.f); a0.w = fmaxf(a0.w, 0.f);
        a1.x = fmaxf(a1.x, 0.f); a1.y = fmaxf(a1.y, 0.f);
        a1.z = fmaxf(a1.z, 0.f); a1.w = fmaxf(a1.w, 0.f);
    }
    dst[node * 24 + 2 * c] = a0;
    dst[node * 24 + 2 * c + 1] = a1;
}

// ---------------- fused mean-pool + head GEMM (one block per graph) ----------------
__global__ __launch_bounds__(96) void k_poolhead(const float* __restrict__ Wlin,
                                                 float* __restrict__ out) {
    __shared__ float p[C];
    int g = blockIdx.x;
    int c = threadIdx.x;                 // 0..95 channel
    int beg = g_gstart[g], end = g_gstart[g + 1];
    float acc = 0.f;
    for (int n = beg; n < end; n++)
        acc += g_agg[(size_t)n * C + c];
    float cnt = (float)(end - beg);
    p[c] = acc / fmaxf(cnt, 1.0f);
    __syncthreads();
    if (c < OC) {
        float s = 0.f;
#pragma unroll
        for (int k = 0; k < C; k++)
            s = fmaf(p[k], __ldg(Wlin + k * OC + c), s);
        out[g * OC + c] = s;
    }
}

// ---------------- launch ----------------
extern "C" void kernel_launch(void* const* d_in, const int* in_sizes, int n_in,
                              void* d_out, int out_size) {
    const float* x     = (const float*)d_in[0];
    const int*   ei    = (const int*)d_in[1];     // int32 (JAX x64 disabled)
    const int*   batch = (const int*)d_in[2];     // int32
    const float* W1    = (const float*)d_in[3];
    const float* b1    = (const float*)d_in[4];
    const float* W2    = (const float*)d_in[5];
    const float* b2    = (const float*)d_in[6];
    const float* W3    = (const float*)d_in[7];
    const float* b3    = (const float*)d_in[8];
    const float* Wlin  = (const float*)d_in[9];
    float* out = (float*)d_out;

    const int TB = 256;
    int gN  = (NN + TB - 1) / TB;
    int gE  = (NE + TB - 1) / TB;
    int gNC = (NN * 12 + TB - 1) / TB;
    int gGemm = (NN + 63) / 64;

    // CSR build interleaved with layer-1 GEMM (gemm1 independent of CSR;
    // placed at launch index 3 so the ncu window profiles it)
    k_prelude<<<gN, TB>>>(batch);           // 0
    k_hist<<<gE, TB>>>(ei);                 // 1
    k_scan1<<<NBLK, 1024>>>();              // 2
    k_gemm<<<gGemm, 96>>>(x, W1, 0);        // 3  <- ncu window
    k_scan23<<<NBLK, 1024>>>();             // 4
    k_fill<<<gE, TB>>>(ei);                 // 5

    // layer 1 aggregation
    k_gather<<<gNC, TB>>>(b1, 1);           // 6
    // layer 2
    k_gemm<<<gGemm, 96>>>(nullptr, W2, 1);
    k_gather<<<gNC, TB>>>(b2, 1);
    // layer 3
    k_gemm<<<gGemm, 96>>>(nullptr, W3, 1);
    k_gather<<<gNC, TB>>>(b3, 0);

    // pooled mean + head
    k_poolhead<<<NG, 96>>>(Wlin, out);
}